// round 1
// baseline (speedup 1.0000x reference)
#include <cuda_runtime.h>
#include <math.h>
#include <float.h>

// Problem constants (from reference: hidden [4,4096,2048], weight [256,2048])
#define T_TOKENS 16384
#define HDIM     2048
#define NEXP     256
#define TOPK     8
#define NGROUP   8
#define TOPKG    4

// Scratch: sigmoid(router_logits)  [T, E]  (16 MB, static device global — allowed)
__device__ float g_scores[(size_t)T_TOKENS * NEXP];

// ---------------------------------------------------------------------------
// Kernel 1: fp32 SGEMM  scores = sigmoid(x @ W^T)
//   x: [T, H] row-major,  W: [E, H] row-major  ->  scores[t, e]
//   BM=128 BN=128 BK=16, 256 threads, 8x8 microtile / thread
// ---------------------------------------------------------------------------
#define BM 128
#define BN 128
#define BK 16

__global__ __launch_bounds__(256) void gemm_sigmoid_kernel(
    const float* __restrict__ x, const float* __restrict__ w)
{
    __shared__ float As[BK][BM];
    __shared__ float Bs[BK][BN];

    const int tid = threadIdx.x;
    const int tx  = tid & 15;       // 0..15
    const int ty  = tid >> 4;       // 0..15

    const int bm = blockIdx.y * BM; // token tile
    const int bn = blockIdx.x * BN; // expert tile

    const float* Ag = x + (size_t)bm * HDIM;
    const float* Bg = w + (size_t)bn * HDIM;

    float c[8][8];
    #pragma unroll
    for (int i = 0; i < 8; i++)
        #pragma unroll
        for (int j = 0; j < 8; j++) c[i][j] = 0.0f;

    for (int k0 = 0; k0 < HDIM; k0 += BK) {
        // Load A tile: 128 rows x 16 cols = 512 float4, 2 per thread
        #pragma unroll
        for (int it = 0; it < 2; it++) {
            int idx = tid + it * 256;
            int row = idx >> 2;
            int c4  = idx & 3;
            float4 v = *(const float4*)(Ag + (size_t)row * HDIM + k0 + c4 * 4);
            As[c4 * 4 + 0][row] = v.x;
            As[c4 * 4 + 1][row] = v.y;
            As[c4 * 4 + 2][row] = v.z;
            As[c4 * 4 + 3][row] = v.w;
        }
        // Load B tile: 128 experts x 16 cols (B[k][n] = W[n][k])
        #pragma unroll
        for (int it = 0; it < 2; it++) {
            int idx = tid + it * 256;
            int row = idx >> 2;
            int c4  = idx & 3;
            float4 v = *(const float4*)(Bg + (size_t)row * HDIM + k0 + c4 * 4);
            Bs[c4 * 4 + 0][row] = v.x;
            Bs[c4 * 4 + 1][row] = v.y;
            Bs[c4 * 4 + 2][row] = v.z;
            Bs[c4 * 4 + 3][row] = v.w;
        }
        __syncthreads();

        #pragma unroll
        for (int kk = 0; kk < BK; kk++) {
            float a[8], b[8];
            *(float4*)&a[0] = *(const float4*)&As[kk][ty * 8];
            *(float4*)&a[4] = *(const float4*)&As[kk][ty * 8 + 4];
            *(float4*)&b[0] = *(const float4*)&Bs[kk][tx * 8];
            *(float4*)&b[4] = *(const float4*)&Bs[kk][tx * 8 + 4];
            #pragma unroll
            for (int i = 0; i < 8; i++)
                #pragma unroll
                for (int j = 0; j < 8; j++)
                    c[i][j] = fmaf(a[i], b[j], c[i][j]);
        }
        __syncthreads();
    }

    // Epilogue: sigmoid, write scores
    #pragma unroll
    for (int i = 0; i < 8; i++) {
        int row = bm + ty * 8 + i;
        #pragma unroll
        for (int j = 0; j < 8; j++) {
            int col = bn + tx * 8 + j;
            float s = 1.0f / (1.0f + expf(-c[i][j]));
            g_scores[(size_t)row * NEXP + col] = s;
        }
    }
}

// ---------------------------------------------------------------------------
// Kernel 2: routing. One warp per token. 256 scores -> 8 lanes' worth each? No:
// lane L owns experts [8L, 8L+8). Group g = experts [32g,32g+32) = lanes [4g,4g+4).
// Exact jax.lax.top_k tie semantics: equal values -> lower index wins.
// Output: out[0 : T*8] = topk_idx (as float), out[T*8 : 2*T*8] = topk_weight.
// ---------------------------------------------------------------------------
__global__ __launch_bounds__(256) void route_kernel(
    const float* __restrict__ bias, float* __restrict__ out)
{
    const unsigned FULL = 0xffffffffu;
    const int warp = threadIdx.x >> 5;
    const int lane = threadIdx.x & 31;
    const int t = blockIdx.x * 8 + warp;

    const float* sp = g_scores + (size_t)t * NEXP + lane * 8;
    float s[8], ch[8];
    {
        float4 v0 = *(const float4*)(sp);
        float4 v1 = *(const float4*)(sp + 4);
        s[0]=v0.x; s[1]=v0.y; s[2]=v0.z; s[3]=v0.w;
        s[4]=v1.x; s[5]=v1.y; s[6]=v1.z; s[7]=v1.w;
        const float* bp = bias + lane * 8;
        float4 b0 = *(const float4*)(bp);
        float4 b1 = *(const float4*)(bp + 4);
        ch[0]=s[0]+b0.x; ch[1]=s[1]+b0.y; ch[2]=s[2]+b0.z; ch[3]=s[3]+b0.w;
        ch[4]=s[4]+b1.x; ch[5]=s[5]+b1.y; ch[6]=s[6]+b1.z; ch[7]=s[7]+b1.w;
    }

    // ---- per-lane top2 of biased scores ----
    float m1 = -FLT_MAX, m2 = -FLT_MAX;
    #pragma unroll
    for (int j = 0; j < 8; j++) {
        float v = ch[j];
        if (v > m1) { m2 = m1; m1 = v; }
        else if (v > m2) { m2 = v; }
    }
    // ---- reduce top2 across the 4 lanes of each group ----
    #pragma unroll
    for (int off = 1; off < 4; off <<= 1) {
        float om1 = __shfl_xor_sync(FULL, m1, off);
        float om2 = __shfl_xor_sync(FULL, m2, off);
        if (om1 > m1) { m2 = fmaxf(m1, om2); m1 = om1; }
        else          { m2 = fmaxf(m2, om1); }
    }
    float gs = m1 + m2;   // group score (valid on every lane of the quad)

    // ---- gather all 8 group scores into every lane ----
    float gsv[8];
    #pragma unroll
    for (int g = 0; g < 8; g++) gsv[g] = __shfl_sync(FULL, gs, g * 4);

    // ---- top-4 groups (tie -> lower group index) ----
    unsigned gmask = 0;
    #pragma unroll
    for (int r = 0; r < TOPKG; r++) {
        float bv = -FLT_MAX; int bi = 0;
        #pragma unroll
        for (int g = 0; g < 8; g++) {
            bool used = (gmask >> g) & 1u;
            if (!used && gsv[g] > bv) { bv = gsv[g]; bi = g; }
        }
        gmask |= (1u << bi);
    }

    // ---- masked candidate scores (masked groups -> exactly 0.0, like ref) ----
    float tmp[8];
    bool gon = (gmask >> (lane >> 2)) & 1u;
    #pragma unroll
    for (int j = 0; j < 8; j++) tmp[j] = gon ? ch[j] : 0.0f;

    // ---- iterative top-8 over 256 entries (tie -> lower expert index) ----
    int   idxs[TOPK];
    float wts[TOPK];
    float wsum = 0.0f;
    #pragma unroll
    for (int r = 0; r < TOPK; r++) {
        float bv = -FLT_MAX; int bj = 0;
        #pragma unroll
        for (int j = 0; j < 8; j++)
            if (tmp[j] > bv) { bv = tmp[j]; bj = j; }   // strict > keeps lowest j on ties
        int gi = lane * 8 + bj;
        #pragma unroll
        for (int off = 16; off > 0; off >>= 1) {
            float ov = __shfl_xor_sync(FULL, bv, off);
            int   oi = __shfl_xor_sync(FULL, gi, off);
            if (ov > bv || (ov == bv && oi < gi)) { bv = ov; gi = oi; }
        }
        // weight from UNbiased score; owning lane also retires the entry
        float myw = s[gi & 7];
        float wv = __shfl_sync(FULL, myw, gi >> 3);
        if ((gi >> 3) == lane) tmp[gi & 7] = -FLT_MAX;
        idxs[r] = gi;
        wts[r]  = wv;
        wsum   += wv;
    }

    if (lane == 0) {
        float denom = wsum + 1e-20f;
        #pragma unroll
        for (int r = 0; r < TOPK; r++) {
            out[(size_t)t * TOPK + r] = (float)idxs[r];
            out[(size_t)T_TOKENS * TOPK + (size_t)t * TOPK + r] =
                (wts[r] / denom) * 2.5f;
        }
    }
}

// ---------------------------------------------------------------------------
extern "C" void kernel_launch(void* const* d_in, const int* in_sizes, int n_in,
                              void* d_out, int out_size)
{
    const float* x    = (const float*)d_in[0];   // [4,4096,2048]
    const float* w    = (const float*)d_in[1];   // [256,2048]
    const float* bias = (const float*)d_in[2];   // [256]
    float* out = (float*)d_out;

    dim3 grid(NEXP / BN, T_TOKENS / BM);   // (2, 128)
    gemm_sigmoid_kernel<<<grid, 256>>>(x, w);
    route_kernel<<<T_TOKENS / 8, 256>>>(bias, out);
}